// round 16
// baseline (speedup 1.0000x reference)
#include <cuda_runtime.h>
#include <cuda_bf16.h>
#include <cuda_fp16.h>

// ---------------------------------------------------------------------------
// GAT 3-layer + PairNorm. N=50000 nodes, E=800000 edges (+N self loops).
//   - CSR build (hist -> 3-kernel scan -> scatter) on a FORKED stream,
//     overlapped with wconv + layer-1 HMMA GEMM; joined before aggr1.
//   - W pre-converted to fp16 once. Per layer: HMMA (mma.sync m16n8k16) GEMM,
//     whole-K smem staging, PairNorm+ReLU fused into the A-load (warp-reduced
//     row norm), smem-staged accumulators -> shuffle-reduced attention
//     epilogue + fp16 feature output -> softmax aggregation that computes
//     edge weights IN-KERNEL (per-warp smem staging over the warp's
//     contiguous CSR range; each edge's exp computed exactly once) and
//     gathers fp16 features 16B/lane; fused column-sum.
//   - Layer 3 fuses head-mean + bias, writes d_out directly.
// ---------------------------------------------------------------------------

#define MAXN 50000
#define MAXE 1000000   // E + N with margin

__device__ __align__(16) __half g_xh[MAXN * 128];
__device__ __align__(16) float g_agg[MAXN * 128];
__device__ __align__(16) float g_als[MAXN * 2];
__device__ __align__(16) float g_ald[MAXN * 2];
__device__ __align__(16) float g_cs[2][128];
__device__ __align__(16) __half g_w16[128 * 128 * 2 + 128 * 32];
__device__ int g_cnt[MAXN + 1];
__device__ int g_off[MAXN + 1];
__device__ int g_cur[MAXN];
__device__ int g_csr[MAXE];
__device__ int g_dste[MAXE];
__device__ int g_bsum[256];
__device__ int g_bpre[256];
__device__ int g_is64;

__device__ __forceinline__ int edge_val(const void* ei, int idx) {
    if (g_is64) return (int)((const long long*)ei)[idx];
    return ((const int*)ei)[idx];
}

__device__ __forceinline__ float lrelu(float x) { return fmaxf(x, 0.2f * x); }

// ---------------------------------------------------------------------------
__global__ void wconv_kernel(const float* __restrict__ W1, const float* __restrict__ W2,
                             const float* __restrict__ W3, __half* __restrict__ w16) {
    int i = blockIdx.x * 256 + threadIdx.x;
    if (i < 16384) w16[i] = __float2half(W1[i]);
    else if (i < 32768) w16[i] = __float2half(W2[i - 16384]);
    else if (i < 36864) w16[i] = __float2half(W3[i - 32768]);
}

// ---------------------------------------------------------------------------
// Histogram of destinations; embeds the edge-dtype probe.
// ---------------------------------------------------------------------------
__global__ void hist_kernel(const void* ei, int E, int Etot, int N, int* cnt) {
    __shared__ int sis64;
    if (threadIdx.x < 32) {
        const long long* p = (const long long*)ei;
        long long v = p[threadIdx.x];
        int ok = (v >= 0 && v < (long long)N);
        unsigned b = __ballot_sync(0xffffffffu, ok);
        if (threadIdx.x == 0) {
            sis64 = (b == 0xffffffffu) ? 1 : 0;
            if (blockIdx.x == 0) g_is64 = sis64;
        }
    }
    __syncthreads();
    int e = blockIdx.x * blockDim.x + threadIdx.x;
    if (e >= Etot) return;
    int dst;
    if (e < E) dst = sis64 ? (int)((const long long*)ei)[E + e] : ((const int*)ei)[E + e];
    else       dst = e - E;
    atomicAdd(&cnt[dst], 1);
}

// ---------------------------------------------------------------------------
// Decoupled 3-kernel scan
// ---------------------------------------------------------------------------
__global__ void scan_bsum_kernel(const int* __restrict__ cnt, int* __restrict__ bsum, int n) {
    int t = threadIdx.x;
    int i = blockIdx.x * 256 + t;
    int v = (i < n) ? cnt[i] : 0;
#pragma unroll
    for (int o = 16; o > 0; o >>= 1) v += __shfl_down_sync(0xffffffffu, v, o);
    __shared__ int ws[8];
    if ((t & 31) == 0) ws[t >> 5] = v;
    __syncthreads();
    if (t == 0) {
        int s = 0;
#pragma unroll
        for (int w = 0; w < 8; w++) s += ws[w];
        bsum[blockIdx.x] = s;
    }
}

__global__ void scan_bscan_kernel(const int* __restrict__ bsum, int* __restrict__ bpre,
                                  int* __restrict__ off, int nb, int n) {
    __shared__ int sm[256];
    int t = threadIdx.x;
    int v = (t < nb) ? bsum[t] : 0;
    sm[t] = v;
    __syncthreads();
#pragma unroll
    for (int d = 1; d < 256; d <<= 1) {
        int x = (t >= d) ? sm[t - d] : 0;
        __syncthreads();
        sm[t] += x;
        __syncthreads();
    }
    if (t < nb) bpre[t] = sm[t] - v;
    if (t == 255) off[n] = sm[255];
}

__global__ void scan_write_kernel(const int* __restrict__ cnt, const int* __restrict__ bpre,
                                  int* __restrict__ off, int* __restrict__ cur, int n) {
    __shared__ int sm[256];
    int t = threadIdx.x;
    int i = blockIdx.x * 256 + t;
    int v = (i < n) ? cnt[i] : 0;
    sm[t] = v;
    __syncthreads();
#pragma unroll
    for (int d = 1; d < 256; d <<= 1) {
        int x = (t >= d) ? sm[t - d] : 0;
        __syncthreads();
        sm[t] += x;
        __syncthreads();
    }
    if (i < n) {
        int o = bpre[blockIdx.x] + sm[t] - v;
        off[i] = o;
        cur[i] = o;
    }
}

// ---------------------------------------------------------------------------
// Scatter edges into CSR (csr + dste).
// ---------------------------------------------------------------------------
__global__ void scatter_kernel(const void* ei, int E, int Etot, int* cur,
                               int* __restrict__ csr, int* __restrict__ dste) {
    int e = blockIdx.x * blockDim.x + threadIdx.x;
    if (e >= Etot) return;
    int src, dst;
    if (e < E) { src = edge_val(ei, e); dst = edge_val(ei, E + e); }
    else       { src = dst = e - E; }
    int pos = atomicAdd(&cur[dst], 1);
    csr[pos] = src;
    dste[pos] = dst;
}

// ---------------------------------------------------------------------------
// HMMA GEMM: C[N x OW](fp16) = act(A[N x 128]) * W16[128 x OW].
// mma.sync.m16n8k16. Whole K=128 staged. A-load: one row per warp/stripe ->
// PairNorm row norm via full-warp shfl_xor, fused mean-subtract + ReLU.
// 8 warps: OW=128 -> 2x4 warp grid (BM=64); OW=32 -> 8x1 (BM=128).
// Accumulators staged to Csm (overlays Asm/Wsm) -> shuffle-reduced attention
// epilogue + fp16 feature stores. Block 0 zeroes cs_zero[0:128).
// ---------------------------------------------------------------------------
template <int OW, bool PN>
__global__ void __launch_bounds__(256)
gemm_attn_kernel(const float* __restrict__ A,
                 const float* __restrict__ mean_cs,
                 const __half* __restrict__ W16,
                 const float* __restrict__ asrc, const float* __restrict__ adst,
                 __half* __restrict__ C,
                 float* __restrict__ als, float* __restrict__ ald,
                 float* __restrict__ cs_zero, int N) {
    constexpr int NWN = (OW == 128) ? 4 : 1;
    constexpr int BM  = (OW == 128) ? 64 : 128;
    constexpr int NWM = 8 / NWN;
    constexpr int WM  = BM / NWM;
    constexpr int MT  = WM / 16;
    constexpr int NT  = (OW / NWN) / 8;
    constexpr int AS  = 128 + 8;
    constexpr int WS  = OW + 8;
    constexpr int CS  = OW + 4;

    extern __shared__ __align__(16) char smraw[];
    __half* Asm = (__half*)smraw;
    __half* Wsm = (__half*)(smraw + (size_t)BM * AS * 2);
    float*  Csm = (float*)smraw;
    __shared__ __align__(16) float Ms[128];

    int t = threadIdx.x;
    int wid = t >> 5, lane = t & 31;
    int row0 = blockIdx.x * BM;

    if (cs_zero && blockIdx.x == 0 && t < 128) cs_zero[t] = 0.f;
    if (PN) {
        if (t < 128) Ms[t] = mean_cs[t] * (1.0f / (float)N);
        __syncthreads();
    }

#pragma unroll
    for (int k = 0; k < BM / 8; k++) {
        int r = k * 8 + wid;
        int gr = row0 + r;
        float4 v = (gr < N) ? ((const float4*)A)[(size_t)gr * 32 + lane]
                            : make_float4(0.f, 0.f, 0.f, 0.f);
        if (PN) {
            float4 m4 = *(const float4*)&Ms[lane * 4];
            v.x -= m4.x; v.y -= m4.y; v.z -= m4.z; v.w -= m4.w;
            float sq = v.x * v.x + v.y * v.y + v.z * v.z + v.w * v.w;
#pragma unroll
            for (int o = 16; o > 0; o >>= 1) sq += __shfl_xor_sync(0xffffffffu, sq, o);
            float sc = 1.0f / (1e-5f + sqrtf(sq));
            v.x = fmaxf(v.x * sc, 0.f);
            v.y = fmaxf(v.y * sc, 0.f);
            v.z = fmaxf(v.z * sc, 0.f);
            v.w = fmaxf(v.w * sc, 0.f);
        }
        __half2* dst = (__half2*)&Asm[r * AS + lane * 4];
        dst[0] = __float22half2_rn(make_float2(v.x, v.y));
        dst[1] = __float22half2_rn(make_float2(v.z, v.w));
    }
    for (int i = t; i < 128 * (OW / 8); i += 256) {
        int r = i / (OW / 8), c8 = i % (OW / 8);
        *(uint4*)&Wsm[r * WS + c8 * 8] = ((const uint4*)W16)[(size_t)r * (OW / 8) + c8];
    }
    __syncthreads();

    int warpM = wid / NWN, warpN = wid % NWN;
    int m0 = warpM * WM;
    int n0 = warpN * (OW / NWN);
    int lr = lane & 15, lc = lane >> 4;

    float acc[MT][NT][4];
#pragma unroll
    for (int mt = 0; mt < MT; mt++)
#pragma unroll
        for (int nt = 0; nt < NT; nt++)
#pragma unroll
            for (int j = 0; j < 4; j++) acc[mt][nt][j] = 0.f;

    for (int k0 = 0; k0 < 128; k0 += 16) {
        unsigned a[MT][4];
#pragma unroll
        for (int mt = 0; mt < MT; mt++) {
            unsigned addr = (unsigned)__cvta_generic_to_shared(
                &Asm[(m0 + mt * 16 + lr) * AS + k0 + lc * 8]);
            asm volatile("ldmatrix.sync.aligned.m8n8.x4.shared.b16 {%0,%1,%2,%3}, [%4];"
                : "=r"(a[mt][0]), "=r"(a[mt][1]), "=r"(a[mt][2]), "=r"(a[mt][3]) : "r"(addr));
        }
        unsigned b[NT][2];
#pragma unroll
        for (int h = 0; h < NT / 2; h++) {
            unsigned addr = (unsigned)__cvta_generic_to_shared(
                &Wsm[(k0 + lr) * WS + n0 + h * 16 + lc * 8]);
            unsigned r0, r1, r2, r3;
            asm volatile("ldmatrix.sync.aligned.m8n8.x4.trans.shared.b16 {%0,%1,%2,%3}, [%4];"
                : "=r"(r0), "=r"(r1), "=r"(r2), "=r"(r3) : "r"(addr));
            b[2 * h][0] = r0;     b[2 * h][1] = r1;
            b[2 * h + 1][0] = r2; b[2 * h + 1][1] = r3;
        }
#pragma unroll
        for (int mt = 0; mt < MT; mt++)
#pragma unroll
            for (int nt = 0; nt < NT; nt++)
                asm volatile("mma.sync.aligned.m16n8k16.row.col.f32.f16.f16.f32 "
                    "{%0,%1,%2,%3},{%4,%5,%6,%7},{%8,%9},{%0,%1,%2,%3};"
                    : "+f"(acc[mt][nt][0]), "+f"(acc[mt][nt][1]),
                      "+f"(acc[mt][nt][2]), "+f"(acc[mt][nt][3])
                    : "r"(a[mt][0]), "r"(a[mt][1]), "r"(a[mt][2]), "r"(a[mt][3]),
                      "r"(b[nt][0]), "r"(b[nt][1]));
    }
    __syncthreads();
#pragma unroll
    for (int mt = 0; mt < MT; mt++)
#pragma unroll
        for (int nt = 0; nt < NT; nt++) {
            int r = m0 + mt * 16 + (lane >> 2);
            int c = n0 + nt * 8 + (lane & 3) * 2;
            Csm[r * CS + c]           = acc[mt][nt][0];
            Csm[r * CS + c + 1]       = acc[mt][nt][1];
            Csm[(r + 8) * CS + c]     = acc[mt][nt][2];
            Csm[(r + 8) * CS + c + 1] = acc[mt][nt][3];
        }
    __syncthreads();

    constexpr int CT = OW / 8;
    constexpr int RPT = BM / (256 / CT);
    int tx = t % CT, ty = t / CT;
    float av[8], bv[8];
#pragma unroll
    for (int j = 0; j < 8; j++) {
        av[j] = asrc[tx * 8 + j];
        bv[j] = adst[tx * 8 + j];
    }
    int head = (tx * 8) / (OW / 2);

#pragma unroll
    for (int r = 0; r < RPT; r++) {
        int row = ty * RPT + r;
        int gr = row0 + row;
        float4 p0 = *(float4*)&Csm[row * CS + tx * 8];
        float4 p1 = *(float4*)&Csm[row * CS + tx * 8 + 4];
        float s = p0.x * av[0] + p0.y * av[1] + p0.z * av[2] + p0.w * av[3]
                + p1.x * av[4] + p1.y * av[5] + p1.z * av[6] + p1.w * av[7];
        float d = p0.x * bv[0] + p0.y * bv[1] + p0.z * bv[2] + p0.w * bv[3]
                + p1.x * bv[4] + p1.y * bv[5] + p1.z * bv[6] + p1.w * bv[7];
        if (gr < N) {
            __half2 h0 = __float22half2_rn(make_float2(p0.x, p0.y));
            __half2 h1 = __float22half2_rn(make_float2(p0.z, p0.w));
            __half2 h2 = __float22half2_rn(make_float2(p1.x, p1.y));
            __half2 h3 = __float22half2_rn(make_float2(p1.z, p1.w));
            uint4 u;
            u.x = *(unsigned*)&h0; u.y = *(unsigned*)&h1;
            u.z = *(unsigned*)&h2; u.w = *(unsigned*)&h3;
            *(uint4*)&C[(size_t)gr * OW + tx * 8] = u;
        }
#pragma unroll
        for (int o = CT / 4; o > 0; o >>= 1) {
            s += __shfl_down_sync(0xffffffffu, s, o, CT / 2);
            d += __shfl_down_sync(0xffffffffu, d, o, CT / 2);
        }
        if ((tx == 0 || tx == CT / 2) && gr < N) {
            als[gr * 2 + head] = s;
            ald[gr * 2 + head] = d;
        }
    }
}

// ---------------------------------------------------------------------------
// Softmax aggregation with IN-KERNEL edge weights. A warp's nodes are
// consecutive -> its CSR range [off[first], off[first+NPW]) is contiguous.
// Per 64-edge chunk: lanes compute softmax weights (one exp-pair per edge,
// computed exactly once) + stage (w0,w1,src) in per-warp smem (__syncwarp);
// then each L-lane subgroup gathers its node's slice of the chunk reading
// weights via broadcast LDS. fp16 features, 16B per lane. Fused column-sum
// for non-FINAL layers; FINAL fuses head-mean + bias -> d_out.
// ---------------------------------------------------------------------------
template <int HD, bool FINAL>
__global__ void __launch_bounds__(256)
aggr_kernel(const __half* __restrict__ xh,
            const float* __restrict__ als, const float* __restrict__ ald,
            const int* __restrict__ off, const int* __restrict__ csr,
            const int* __restrict__ dste,
            const float* __restrict__ bias,
            float* __restrict__ out, float* __restrict__ cs, int N) {
    constexpr int L = (HD * 2) / 16;   // lanes per node: 16 (HD=128) or 4 (HD=32)
    constexpr int NPW = 32 / L;        // nodes per warp: 2 or 8
    constexpr int D = HD / 2;          // features per head
    constexpr int CHUNK = 64;
    __shared__ float2 sw[8][CHUNK];
    __shared__ int ssrc[8][CHUNK];

    int wib = threadIdx.x >> 5;
    int wid = blockIdx.x * 8 + wib;
    int lane = threadIdx.x & 31;
    int sub = lane / L;
    int lig = lane % L;
    int nfirst = wid * NPW;
    int nreq = nfirst + sub;
    bool valid = nreq < N;
    int n = valid ? nreq : (N - 1);

    int st = off[n], en = off[n + 1];
    int stw = off[min(nfirst, N)];
    int enw = off[min(nfirst + NPW, N)];
    int head = (lig * 8) / D;

    float s0 = 0.f, s1 = 0.f;
    float acc[8];
#pragma unroll
    for (int k = 0; k < 8; k++) acc[k] = 0.f;
    const uint4* x16 = (const uint4*)xh;

    for (int base = stw; base < enw; base += CHUNK) {
        int m = min(CHUNK, enw - base);
        // stage weights: lane j covers edges base+j, base+j+32
#pragma unroll 2
        for (int j = lane; j < m; j += 32) {
            int s = csr[base + j];
            int d = dste[base + j];
            float2 a = ((const float2*)als)[s];
            float2 b = ((const float2*)ald)[d];
            sw[wib][j] = make_float2(__expf(lrelu(a.x + b.x)), __expf(lrelu(a.y + b.y)));
            ssrc[wib][j] = s;
        }
        __syncwarp();
        // gather: subgroup processes its node's slice of this chunk
        int lo = max(st, base), hi = min(en, base + m);
#pragma unroll 4
        for (int i = lo; i < hi; i++) {
            float2 w = sw[wib][i - base];
            int s = ssrc[wib][i - base];
            s0 += w.x; s1 += w.y;
            float ws = head ? w.y : w.x;
            uint4 u = x16[(size_t)s * L + lig];
            float2 f0 = __half22float2(*(__half2*)&u.x);
            float2 f1 = __half22float2(*(__half2*)&u.y);
            float2 f2 = __half22float2(*(__half2*)&u.z);
            float2 f3 = __half22float2(*(__half2*)&u.w);
            acc[0] = fmaf(ws, f0.x, acc[0]);
            acc[1] = fmaf(ws, f0.y, acc[1]);
            acc[2] = fmaf(ws, f1.x, acc[2]);
            acc[3] = fmaf(ws, f1.y, acc[3]);
            acc[4] = fmaf(ws, f2.x, acc[4]);
            acc[5] = fmaf(ws, f2.y, acc[5]);
            acc[6] = fmaf(ws, f3.x, acc[6]);
            acc[7] = fmaf(ws, f3.y, acc[7]);
        }
        __syncwarp();
    }
    float inv = 1.0f / (head ? s1 : s0);
#pragma unroll
    for (int k = 0; k < 8; k++) acc[k] *= inv;

    if (FINAL) {
        float o[8];
#pragma unroll
        for (int k = 0; k < 8; k++) o[k] = __shfl_down_sync(0xffffffffu, acc[k], 2);
        if (valid && lig < 2) {
            float4 r0, r1;
            r0.x = 0.5f * (acc[0] + o[0]) + bias[lig * 8 + 0];
            r0.y = 0.5f * (acc[1] + o[1]) + bias[lig * 8 + 1];
            r0.z = 0.5f * (acc[2] + o[2]) + bias[lig * 8 + 2];
            r0.w = 0.5f * (acc[3] + o[3]) + bias[lig * 8 + 3];
            r1.x = 0.5f * (acc[4] + o[4]) + bias[lig * 8 + 4];
            r1.y = 0.5f * (acc[5] + o[5]) + bias[lig * 8 + 5];
            r1.z = 0.5f * (acc[6] + o[6]) + bias[lig * 8 + 6];
            r1.w = 0.5f * (acc[7] + o[7]) + bias[lig * 8 + 7];
            float4* dst = (float4*)&out[(size_t)n * 16 + lig * 8];
            dst[0] = r0;
            dst[1] = r1;
        }
    } else {
        if (valid) {
            float4* dst = (float4*)&out[(size_t)n * 128 + lig * 8];
            dst[0] = make_float4(acc[0], acc[1], acc[2], acc[3]);
            dst[1] = make_float4(acc[4], acc[5], acc[6], acc[7]);
        }
        __shared__ float csm[16][128];
        float* rowp = csm[wib * 2 + sub];
        if (!valid) {
#pragma unroll
            for (int k = 0; k < 8; k++) acc[k] = 0.f;
        }
        ((float4*)&rowp[lig * 8])[0] = make_float4(acc[0], acc[1], acc[2], acc[3]);
        ((float4*)&rowp[lig * 8])[1] = make_float4(acc[4], acc[5], acc[6], acc[7]);
        __syncthreads();
        int t = threadIdx.x;
        if (t < 128) {
            float s = 0.f;
#pragma unroll
            for (int w = 0; w < 16; w++) s += csm[w][t];
            atomicAdd(&cs[t], s);
        }
    }
}

// ---------------------------------------------------------------------------
extern "C" void kernel_launch(void* const* d_in, const int* in_sizes, int n_in,
                              void* d_out, int out_size) {
    const float* x   = (const float*)d_in[0];
    const void*  ei  = d_in[1];
    const float* W1  = (const float*)d_in[2];
    const float* as1 = (const float*)d_in[3];
    const float* ad1 = (const float*)d_in[4];
    const float* W2  = (const float*)d_in[6];
    const float* as2 = (const float*)d_in[7];
    const float* ad2 = (const float*)d_in[8];
    const float* W3  = (const float*)d_in[10];
    const float* as3 = (const float*)d_in[11];
    const float* ad3 = (const float*)d_in[12];
    const float* b3  = (const float*)d_in[13];

    int N = in_sizes[0] / 128;
    int E = in_sizes[1] / 2;
    int Etot = E + N;

    __half *xh, *w16;
    float *agg, *als, *ald, *cs;
    int *cnt, *off, *cur, *csr, *dste, *bsum, *bpre;
    cudaGetSymbolAddress((void**)&xh, g_xh);
    cudaGetSymbolAddress((void**)&w16, g_w16);
    cudaGetSymbolAddress((void**)&agg, g_agg);
    cudaGetSymbolAddress((void**)&als, g_als);
    cudaGetSymbolAddress((void**)&ald, g_ald);
    cudaGetSymbolAddress((void**)&cs, g_cs);
    cudaGetSymbolAddress((void**)&cnt, g_cnt);
    cudaGetSymbolAddress((void**)&off, g_off);
    cudaGetSymbolAddress((void**)&cur, g_cur);
    cudaGetSymbolAddress((void**)&csr, g_csr);
    cudaGetSymbolAddress((void**)&dste, g_dste);
    cudaGetSymbolAddress((void**)&bsum, g_bsum);
    cudaGetSymbolAddress((void**)&bpre, g_bpre);
    float* cs0 = cs;
    float* cs1 = cs + 128;

    const int SMEM128 = (64 * 136 + 128 * 136) * 2;
    const int SMEM32  = (128 * 136 + 128 * 40) * 2;
    cudaFuncSetAttribute(gemm_attn_kernel<128, false>,
                         cudaFuncAttributeMaxDynamicSharedMemorySize, SMEM128);
    cudaFuncSetAttribute(gemm_attn_kernel<128, true>,
                         cudaFuncAttributeMaxDynamicSharedMemorySize, SMEM128);
    cudaFuncSetAttribute(gemm_attn_kernel<32, true>,
                         cudaFuncAttributeMaxDynamicSharedMemorySize, SMEM32);

    const int TB = 256;
    int aggr_blocks   = (N / 2 + 7) / 8;
    int aggr_blocks8  = (N / 8 + 7) / 8;
    int gemm_blocks   = (N + 63) / 64;
    int gemm_blocks3  = (N + 127) / 128;
    int eb            = (Etot + TB - 1) / TB;
    int nb1 = (N + 255) / 256;             // 196 <= 256

    cudaStream_t s1;
    cudaStreamCreateWithFlags(&s1, cudaStreamNonBlocking);
    cudaEvent_t e1, e2;
    cudaEventCreateWithFlags(&e1, cudaEventDisableTiming);
    cudaEventCreateWithFlags(&e2, cudaEventDisableTiming);

    cudaMemsetAsync(cnt, 0, (size_t)N * sizeof(int));
    cudaEventRecord(e1, 0);
    cudaStreamWaitEvent(s1, e1, 0);

    // s1: CSR build chain
    hist_kernel<<<eb, TB, 0, s1>>>(ei, E, Etot, N, cnt);
    scan_bsum_kernel<<<nb1, 256, 0, s1>>>(cnt, bsum, N);
    // stream 0: wconv + GEMM layer 1 (kernel idx 3 <- ncu capture window)
    wconv_kernel<<<144, 256>>>(W1, W2, W3, w16);
    gemm_attn_kernel<128, false><<<gemm_blocks, TB, SMEM128>>>(
        x, nullptr, w16, as1, ad1, xh, als, ald, cs0, N);
    // s1: finish CSR
    scan_bscan_kernel<<<1, 256, 0, s1>>>(bsum, bpre, off, nb1, N);
    scan_write_kernel<<<nb1, 256, 0, s1>>>(cnt, bpre, off, cur, N);
    scatter_kernel<<<eb, TB, 0, s1>>>(ei, E, Etot, cur, csr, dste);
    cudaEventRecord(e2, s1);
    cudaStreamWaitEvent(0, e2, 0);   // join

    // ---- layer 1 aggregation (in-kernel edge weights) ----
    aggr_kernel<128, false><<<aggr_blocks, TB>>>(xh, als, ald, off, csr, dste,
                                                 nullptr, agg, cs0, N);

    // ---- layer 2 (PairNorm fused into GEMM A-load) ----
    gemm_attn_kernel<128, true><<<gemm_blocks, TB, SMEM128>>>(
        agg, cs0, w16 + 16384, as2, ad2, xh, als, ald, cs1, N);
    aggr_kernel<128, false><<<aggr_blocks, TB>>>(xh, als, ald, off, csr, dste,
                                                 nullptr, agg, cs1, N);

    // ---- layer 3 (writes d_out with head-mean + bias) ----
    gemm_attn_kernel<32, true><<<gemm_blocks3, TB, SMEM32>>>(
        agg, cs1, w16 + 32768, as3, ad3, xh, als, ald, nullptr, N);
    aggr_kernel<32, true><<<aggr_blocks8, TB>>>(xh, als, ald, off, csr, dste,
                                                b3, (float*)d_out, nullptr, N);
}

// round 17
// speedup vs baseline: 1.0721x; 1.0721x over previous
#include <cuda_runtime.h>
#include <cuda_bf16.h>
#include <cuda_fp16.h>

// ---------------------------------------------------------------------------
// GAT 3-layer + PairNorm. N=50000 nodes, E=800000 edges (+N self loops).
//   - CSR build (hist -> 3-kernel scan -> scatter) on a FORKED stream,
//     overlapped with wconv + layer-1 HMMA GEMM; joined via event before ew1.
//   - W pre-converted to fp16 once. Per layer: HMMA (mma.sync m16n8k16) GEMM,
//     whole-K smem staging, PairNorm+ReLU fused into the A-load (fp16 agg
//     input for layers 2/3; fp32 x for layer 1), smem-staged accumulators ->
//     shuffle-reduced attention epilogue + fp16 feature output ->
//     edge-parallel weight precompute -> softmax aggregation with precomputed
//     weights, fp16 gathers, fp16 agg output, fused fp32 column-sum.
//   - Layer 3 fuses head-mean + bias, writes d_out (fp32) directly.
// ---------------------------------------------------------------------------

#define MAXN 50000
#define MAXE 1000000   // E + N with margin

__device__ __align__(16) __half g_xh[MAXN * 128];
__device__ __align__(16) __half g_agg[MAXN * 128];
__device__ __align__(16) float g_als[MAXN * 2];
__device__ __align__(16) float g_ald[MAXN * 2];
__device__ __align__(16) float g_cs[2][128];
__device__ __align__(16) float2 g_w2[MAXE];
__device__ __align__(16) __half g_w16[128 * 128 * 2 + 128 * 32];
__device__ int g_cnt[MAXN + 1];
__device__ int g_off[MAXN + 1];
__device__ int g_cur[MAXN];
__device__ int g_csr[MAXE];
__device__ int g_dste[MAXE];
__device__ int g_bsum[256];
__device__ int g_bpre[256];
__device__ int g_is64;

__device__ __forceinline__ int edge_val(const void* ei, int idx) {
    if (g_is64) return (int)((const long long*)ei)[idx];
    return ((const int*)ei)[idx];
}

__device__ __forceinline__ float lrelu(float x) { return fmaxf(x, 0.2f * x); }

// ---------------------------------------------------------------------------
__global__ void wconv_kernel(const float* __restrict__ W1, const float* __restrict__ W2,
                             const float* __restrict__ W3, __half* __restrict__ w16) {
    int i = blockIdx.x * 256 + threadIdx.x;
    if (i < 16384) w16[i] = __float2half(W1[i]);
    else if (i < 32768) w16[i] = __float2half(W2[i - 16384]);
    else if (i < 36864) w16[i] = __float2half(W3[i - 32768]);
}

// ---------------------------------------------------------------------------
// Histogram of destinations; embeds the edge-dtype probe.
// ---------------------------------------------------------------------------
__global__ void hist_kernel(const void* ei, int E, int Etot, int N, int* cnt) {
    __shared__ int sis64;
    if (threadIdx.x < 32) {
        const long long* p = (const long long*)ei;
        long long v = p[threadIdx.x];
        int ok = (v >= 0 && v < (long long)N);
        unsigned b = __ballot_sync(0xffffffffu, ok);
        if (threadIdx.x == 0) {
            sis64 = (b == 0xffffffffu) ? 1 : 0;
            if (blockIdx.x == 0) g_is64 = sis64;
        }
    }
    __syncthreads();
    int e = blockIdx.x * blockDim.x + threadIdx.x;
    if (e >= Etot) return;
    int dst;
    if (e < E) dst = sis64 ? (int)((const long long*)ei)[E + e] : ((const int*)ei)[E + e];
    else       dst = e - E;
    atomicAdd(&cnt[dst], 1);
}

// ---------------------------------------------------------------------------
// Decoupled 3-kernel scan
// ---------------------------------------------------------------------------
__global__ void scan_bsum_kernel(const int* __restrict__ cnt, int* __restrict__ bsum, int n) {
    int t = threadIdx.x;
    int i = blockIdx.x * 256 + t;
    int v = (i < n) ? cnt[i] : 0;
#pragma unroll
    for (int o = 16; o > 0; o >>= 1) v += __shfl_down_sync(0xffffffffu, v, o);
    __shared__ int ws[8];
    if ((t & 31) == 0) ws[t >> 5] = v;
    __syncthreads();
    if (t == 0) {
        int s = 0;
#pragma unroll
        for (int w = 0; w < 8; w++) s += ws[w];
        bsum[blockIdx.x] = s;
    }
}

__global__ void scan_bscan_kernel(const int* __restrict__ bsum, int* __restrict__ bpre,
                                  int* __restrict__ off, int nb, int n) {
    __shared__ int sm[256];
    int t = threadIdx.x;
    int v = (t < nb) ? bsum[t] : 0;
    sm[t] = v;
    __syncthreads();
#pragma unroll
    for (int d = 1; d < 256; d <<= 1) {
        int x = (t >= d) ? sm[t - d] : 0;
        __syncthreads();
        sm[t] += x;
        __syncthreads();
    }
    if (t < nb) bpre[t] = sm[t] - v;
    if (t == 255) off[n] = sm[255];
}

__global__ void scan_write_kernel(const int* __restrict__ cnt, const int* __restrict__ bpre,
                                  int* __restrict__ off, int* __restrict__ cur, int n) {
    __shared__ int sm[256];
    int t = threadIdx.x;
    int i = blockIdx.x * 256 + t;
    int v = (i < n) ? cnt[i] : 0;
    sm[t] = v;
    __syncthreads();
#pragma unroll
    for (int d = 1; d < 256; d <<= 1) {
        int x = (t >= d) ? sm[t - d] : 0;
        __syncthreads();
        sm[t] += x;
        __syncthreads();
    }
    if (i < n) {
        int o = bpre[blockIdx.x] + sm[t] - v;
        off[i] = o;
        cur[i] = o;
    }
}

// ---------------------------------------------------------------------------
// Scatter edges into CSR (csr + dste; weights via ew_kernel).
// ---------------------------------------------------------------------------
__global__ void scatter_kernel(const void* ei, int E, int Etot, int* cur,
                               int* __restrict__ csr, int* __restrict__ dste) {
    int e = blockIdx.x * blockDim.x + threadIdx.x;
    if (e >= Etot) return;
    int src, dst;
    if (e < E) { src = edge_val(ei, e); dst = edge_val(ei, E + e); }
    else       { src = dst = e - E; }
    int pos = atomicAdd(&cur[dst], 1);
    csr[pos] = src;
    dste[pos] = dst;
}

// ---------------------------------------------------------------------------
// Edge-parallel softmax-weight precompute (all layers)
// ---------------------------------------------------------------------------
__global__ void ew_kernel(const int* __restrict__ csr, const int* __restrict__ dste,
                          const float* __restrict__ als, const float* __restrict__ ald,
                          float2* __restrict__ w2, int Etot) {
    int e = blockIdx.x * blockDim.x + threadIdx.x;
    if (e >= Etot) return;
    int s = csr[e], d = dste[e];
    float2 a = ((const float2*)als)[s];
    float2 b = ((const float2*)ald)[d];
    w2[e] = make_float2(__expf(lrelu(a.x + b.x)), __expf(lrelu(a.y + b.y)));
}

// ---------------------------------------------------------------------------
// HMMA GEMM: C[N x OW](fp16) = act(A[N x 128]) * W16[128 x OW].
// mma.sync.m16n8k16. Whole K=128 staged. A-load: one row per warp/stripe;
// PN=true reads fp16 agg (4 halves/lane), PN=false reads fp32 x (float4/lane);
// PairNorm row norm via full-warp shfl_xor, fused mean-subtract + ReLU.
// 8 warps: OW=128 -> 2x4 warp grid (BM=64); OW=32 -> 8x1 (BM=128).
// Accumulators staged to Csm (overlays Asm/Wsm) -> shuffle-reduced attention
// epilogue + fp16 feature stores. Block 0 zeroes cs_zero[0:128).
// ---------------------------------------------------------------------------
template <int OW, bool PN>
__global__ void __launch_bounds__(256)
gemm_attn_kernel(const void* __restrict__ Ain,
                 const float* __restrict__ mean_cs,
                 const __half* __restrict__ W16,
                 const float* __restrict__ asrc, const float* __restrict__ adst,
                 __half* __restrict__ C,
                 float* __restrict__ als, float* __restrict__ ald,
                 float* __restrict__ cs_zero, int N) {
    constexpr int NWN = (OW == 128) ? 4 : 1;
    constexpr int BM  = (OW == 128) ? 64 : 128;
    constexpr int NWM = 8 / NWN;
    constexpr int WM  = BM / NWM;
    constexpr int MT  = WM / 16;
    constexpr int NT  = (OW / NWN) / 8;
    constexpr int AS  = 128 + 8;
    constexpr int WS  = OW + 8;
    constexpr int CS  = OW + 4;

    extern __shared__ __align__(16) char smraw[];
    __half* Asm = (__half*)smraw;
    __half* Wsm = (__half*)(smraw + (size_t)BM * AS * 2);
    float*  Csm = (float*)smraw;
    __shared__ __align__(16) float Ms[128];

    int t = threadIdx.x;
    int wid = t >> 5, lane = t & 31;
    int row0 = blockIdx.x * BM;

    if (cs_zero && blockIdx.x == 0 && t < 128) cs_zero[t] = 0.f;
    if (PN) {
        if (t < 128) Ms[t] = mean_cs[t] * (1.0f / (float)N);
        __syncthreads();
    }

#pragma unroll
    for (int k = 0; k < BM / 8; k++) {
        int r = k * 8 + wid;
        int gr = row0 + r;
        float4 v;
        if (PN) {
            // fp16 input: 4 halves per lane
            uint2 u = (gr < N) ? ((const uint2*)Ain)[(size_t)gr * 32 + lane]
                               : make_uint2(0u, 0u);
            float2 f01 = __half22float2(*(__half2*)&u.x);
            float2 f23 = __half22float2(*(__half2*)&u.y);
            v = make_float4(f01.x, f01.y, f23.x, f23.y);
            float4 m4 = *(const float4*)&Ms[lane * 4];
            v.x -= m4.x; v.y -= m4.y; v.z -= m4.z; v.w -= m4.w;
            float sq = v.x * v.x + v.y * v.y + v.z * v.z + v.w * v.w;
#pragma unroll
            for (int o = 16; o > 0; o >>= 1) sq += __shfl_xor_sync(0xffffffffu, sq, o);
            float sc = 1.0f / (1e-5f + sqrtf(sq));
            v.x = fmaxf(v.x * sc, 0.f);
            v.y = fmaxf(v.y * sc, 0.f);
            v.z = fmaxf(v.z * sc, 0.f);
            v.w = fmaxf(v.w * sc, 0.f);
        } else {
            v = (gr < N) ? ((const float4*)Ain)[(size_t)gr * 32 + lane]
                         : make_float4(0.f, 0.f, 0.f, 0.f);
        }
        __half2* dst = (__half2*)&Asm[r * AS + lane * 4];
        dst[0] = __float22half2_rn(make_float2(v.x, v.y));
        dst[1] = __float22half2_rn(make_float2(v.z, v.w));
    }
    for (int i = t; i < 128 * (OW / 8); i += 256) {
        int r = i / (OW / 8), c8 = i % (OW / 8);
        *(uint4*)&Wsm[r * WS + c8 * 8] = ((const uint4*)W16)[(size_t)r * (OW / 8) + c8];
    }
    __syncthreads();

    int warpM = wid / NWN, warpN = wid % NWN;
    int m0 = warpM * WM;
    int n0 = warpN * (OW / NWN);
    int lr = lane & 15, lc = lane >> 4;

    float acc[MT][NT][4];
#pragma unroll
    for (int mt = 0; mt < MT; mt++)
#pragma unroll
        for (int nt = 0; nt < NT; nt++)
#pragma unroll
            for (int j = 0; j < 4; j++) acc[mt][nt][j] = 0.f;

    for (int k0 = 0; k0 < 128; k0 += 16) {
        unsigned a[MT][4];
#pragma unroll
        for (int mt = 0; mt < MT; mt++) {
            unsigned addr = (unsigned)__cvta_generic_to_shared(
                &Asm[(m0 + mt * 16 + lr) * AS + k0 + lc * 8]);
            asm volatile("ldmatrix.sync.aligned.m8n8.x4.shared.b16 {%0,%1,%2,%3}, [%4];"
                : "=r"(a[mt][0]), "=r"(a[mt][1]), "=r"(a[mt][2]), "=r"(a[mt][3]) : "r"(addr));
        }
        unsigned b[NT][2];
#pragma unroll
        for (int h = 0; h < NT / 2; h++) {
            unsigned addr = (unsigned)__cvta_generic_to_shared(
                &Wsm[(k0 + lr) * WS + n0 + h * 16 + lc * 8]);
            unsigned r0, r1, r2, r3;
            asm volatile("ldmatrix.sync.aligned.m8n8.x4.trans.shared.b16 {%0,%1,%2,%3}, [%4];"
                : "=r"(r0), "=r"(r1), "=r"(r2), "=r"(r3) : "r"(addr));
            b[2 * h][0] = r0;     b[2 * h][1] = r1;
            b[2 * h + 1][0] = r2; b[2 * h + 1][1] = r3;
        }
#pragma unroll
        for (int mt = 0; mt < MT; mt++)
#pragma unroll
            for (int nt = 0; nt < NT; nt++)
                asm volatile("mma.sync.aligned.m16n8k16.row.col.f32.f16.f16.f32 "
                    "{%0,%1,%2,%3},{%4,%5,%6,%7},{%8,%9},{%0,%1,%2,%3};"
                    : "+f"(acc[mt][nt][0]), "+f"(acc[mt][nt][1]),
                      "+f"(acc[mt][nt][2]), "+f"(acc[mt][nt][3])
                    : "r"(a[mt][0]), "r"(a[mt][1]), "r"(a[mt][2]), "r"(a[mt][3]),
                      "r"(b[nt][0]), "r"(b[nt][1]));
    }
    __syncthreads();
#pragma unroll
    for (int mt = 0; mt < MT; mt++)
#pragma unroll
        for (int nt = 0; nt < NT; nt++) {
            int r = m0 + mt * 16 + (lane >> 2);
            int c = n0 + nt * 8 + (lane & 3) * 2;
            Csm[r * CS + c]           = acc[mt][nt][0];
            Csm[r * CS + c + 1]       = acc[mt][nt][1];
            Csm[(r + 8) * CS + c]     = acc[mt][nt][2];
            Csm[(r + 8) * CS + c + 1] = acc[mt][nt][3];
        }
    __syncthreads();

    constexpr int CT = OW / 8;
    constexpr int RPT = BM / (256 / CT);
    int tx = t % CT, ty = t / CT;
    float av[8], bv[8];
#pragma unroll
    for (int j = 0; j < 8; j++) {
        av[j] = asrc[tx * 8 + j];
        bv[j] = adst[tx * 8 + j];
    }
    int head = (tx * 8) / (OW / 2);

#pragma unroll
    for (int r = 0; r < RPT; r++) {
        int row = ty * RPT + r;
        int gr = row0 + row;
        float4 p0 = *(float4*)&Csm[row * CS + tx * 8];
        float4 p1 = *(float4*)&Csm[row * CS + tx * 8 + 4];
        float s = p0.x * av[0] + p0.y * av[1] + p0.z * av[2] + p0.w * av[3]
                + p1.x * av[4] + p1.y * av[5] + p1.z * av[6] + p1.w * av[7];
        float d = p0.x * bv[0] + p0.y * bv[1] + p0.z * bv[2] + p0.w * bv[3]
                + p1.x * bv[4] + p1.y * bv[5] + p1.z * bv[6] + p1.w * bv[7];
        if (gr < N) {
            __half2 h0 = __float22half2_rn(make_float2(p0.x, p0.y));
            __half2 h1 = __float22half2_rn(make_float2(p0.z, p0.w));
            __half2 h2 = __float22half2_rn(make_float2(p1.x, p1.y));
            __half2 h3 = __float22half2_rn(make_float2(p1.z, p1.w));
            uint4 u;
            u.x = *(unsigned*)&h0; u.y = *(unsigned*)&h1;
            u.z = *(unsigned*)&h2; u.w = *(unsigned*)&h3;
            *(uint4*)&C[(size_t)gr * OW + tx * 8] = u;
        }
#pragma unroll
        for (int o = CT / 4; o > 0; o >>= 1) {
            s += __shfl_down_sync(0xffffffffu, s, o, CT / 2);
            d += __shfl_down_sync(0xffffffffu, d, o, CT / 2);
        }
        if ((tx == 0 || tx == CT / 2) && gr < N) {
            als[gr * 2 + head] = s;
            ald[gr * 2 + head] = d;
        }
    }
}

// ---------------------------------------------------------------------------
// Softmax aggregation, precomputed weights, fp16 features, 16B per lane.
// Non-FINAL writes fp16 agg; FINAL writes fp32 d_out with head-mean + bias.
// Column sums accumulated in fp32 from registers (unchanged precision).
// ---------------------------------------------------------------------------
template <int HD, bool FINAL>
__global__ void __launch_bounds__(256)
aggr_kernel(const __half* __restrict__ xh,
            const float2* __restrict__ w2,
            const int* __restrict__ off, const int* __restrict__ csr,
            const float* __restrict__ bias,
            void* __restrict__ outv, float* __restrict__ cs, int N) {
    constexpr int L = (HD * 2) / 16;   // lanes per node: 16 (HD=128) or 4 (HD=32)
    constexpr int NPW = 32 / L;        // nodes per warp: 2 or 8
    constexpr int D = HD / 2;          // features per head
    int wib = threadIdx.x >> 5;
    int wid = blockIdx.x * 8 + wib;
    int lane = threadIdx.x & 31;
    int sub = lane / L;
    int lig = lane % L;
    int nreq = wid * NPW + sub;
    bool valid = nreq < N;
    int n = valid ? nreq : (N - 1);

    int st = off[n], en = off[n + 1];
    int head = (lig * 8) / D;

    float s0 = 0.f, s1 = 0.f;
    float acc[8];
#pragma unroll
    for (int k = 0; k < 8; k++) acc[k] = 0.f;
    const uint4* x16 = (const uint4*)xh;

#pragma unroll 4
    for (int i = st; i < en; i++) {
        int s = csr[i];
        float2 w = w2[i];
        s0 += w.x; s1 += w.y;
        float ws = head ? w.y : w.x;
        uint4 u = x16[(size_t)s * L + lig];
        float2 f0 = __half22float2(*(__half2*)&u.x);
        float2 f1 = __half22float2(*(__half2*)&u.y);
        float2 f2 = __half22float2(*(__half2*)&u.z);
        float2 f3 = __half22float2(*(__half2*)&u.w);
        acc[0] = fmaf(ws, f0.x, acc[0]);
        acc[1] = fmaf(ws, f0.y, acc[1]);
        acc[2] = fmaf(ws, f1.x, acc[2]);
        acc[3] = fmaf(ws, f1.y, acc[3]);
        acc[4] = fmaf(ws, f2.x, acc[4]);
        acc[5] = fmaf(ws, f2.y, acc[5]);
        acc[6] = fmaf(ws, f3.x, acc[6]);
        acc[7] = fmaf(ws, f3.y, acc[7]);
    }
    float inv = 1.0f / (head ? s1 : s0);
#pragma unroll
    for (int k = 0; k < 8; k++) acc[k] *= inv;

    if (FINAL) {
        float* out = (float*)outv;
        float o[8];
#pragma unroll
        for (int k = 0; k < 8; k++) o[k] = __shfl_down_sync(0xffffffffu, acc[k], 2);
        if (valid && lig < 2) {
            float4 r0, r1;
            r0.x = 0.5f * (acc[0] + o[0]) + bias[lig * 8 + 0];
            r0.y = 0.5f * (acc[1] + o[1]) + bias[lig * 8 + 1];
            r0.z = 0.5f * (acc[2] + o[2]) + bias[lig * 8 + 2];
            r0.w = 0.5f * (acc[3] + o[3]) + bias[lig * 8 + 3];
            r1.x = 0.5f * (acc[4] + o[4]) + bias[lig * 8 + 4];
            r1.y = 0.5f * (acc[5] + o[5]) + bias[lig * 8 + 5];
            r1.z = 0.5f * (acc[6] + o[6]) + bias[lig * 8 + 6];
            r1.w = 0.5f * (acc[7] + o[7]) + bias[lig * 8 + 7];
            float4* dst = (float4*)&out[(size_t)n * 16 + lig * 8];
            dst[0] = r0;
            dst[1] = r1;
        }
    } else {
        __half* out = (__half*)outv;
        if (valid) {
            __half2 h0 = __float22half2_rn(make_float2(acc[0], acc[1]));
            __half2 h1 = __float22half2_rn(make_float2(acc[2], acc[3]));
            __half2 h2 = __float22half2_rn(make_float2(acc[4], acc[5]));
            __half2 h3 = __float22half2_rn(make_float2(acc[6], acc[7]));
            uint4 u;
            u.x = *(unsigned*)&h0; u.y = *(unsigned*)&h1;
            u.z = *(unsigned*)&h2; u.w = *(unsigned*)&h3;
            *(uint4*)&out[(size_t)n * 128 + lig * 8] = u;
        }
        __shared__ float csm[16][128];
        float* rowp = csm[wib * 2 + sub];
        if (!valid) {
#pragma unroll
            for (int k = 0; k < 8; k++) acc[k] = 0.f;
        }
        ((float4*)&rowp[lig * 8])[0] = make_float4(acc[0], acc[1], acc[2], acc[3]);
        ((float4*)&rowp[lig * 8])[1] = make_float4(acc[4], acc[5], acc[6], acc[7]);
        __syncthreads();
        int t = threadIdx.x;
        if (t < 128) {
            float s = 0.f;
#pragma unroll
            for (int w = 0; w < 16; w++) s += csm[w][t];
            atomicAdd(&cs[t], s);
        }
    }
}

// ---------------------------------------------------------------------------
extern "C" void kernel_launch(void* const* d_in, const int* in_sizes, int n_in,
                              void* d_out, int out_size) {
    const float* x   = (const float*)d_in[0];
    const void*  ei  = d_in[1];
    const float* W1  = (const float*)d_in[2];
    const float* as1 = (const float*)d_in[3];
    const float* ad1 = (const float*)d_in[4];
    const float* W2  = (const float*)d_in[6];
    const float* as2 = (const float*)d_in[7];
    const float* ad2 = (const float*)d_in[8];
    const float* W3  = (const float*)d_in[10];
    const float* as3 = (const float*)d_in[11];
    const float* ad3 = (const float*)d_in[12];
    const float* b3  = (const float*)d_in[13];

    int N = in_sizes[0] / 128;
    int E = in_sizes[1] / 2;
    int Etot = E + N;

    __half *xh, *w16, *agg;
    float *als, *ald, *cs;
    float2* w2;
    int *cnt, *off, *cur, *csr, *dste, *bsum, *bpre;
    cudaGetSymbolAddress((void**)&xh, g_xh);
    cudaGetSymbolAddress((void**)&w16, g_w16);
    cudaGetSymbolAddress((void**)&agg, g_agg);
    cudaGetSymbolAddress((void**)&als, g_als);
    cudaGetSymbolAddress((void**)&ald, g_ald);
    cudaGetSymbolAddress((void**)&cs, g_cs);
    cudaGetSymbolAddress((void**)&w2, g_w2);
    cudaGetSymbolAddress((void**)&cnt, g_cnt);
    cudaGetSymbolAddress((void**)&off, g_off);
    cudaGetSymbolAddress((void**)&cur, g_cur);
    cudaGetSymbolAddress((void**)&csr, g_csr);
    cudaGetSymbolAddress((void**)&dste, g_dste);
    cudaGetSymbolAddress((void**)&bsum, g_bsum);
    cudaGetSymbolAddress((void**)&bpre, g_bpre);
    float* cs0 = cs;
    float* cs1 = cs + 128;

    const int SMEM128 = (64 * 136 + 128 * 136) * 2;
    const int SMEM32  = (128 * 136 + 128 * 40) * 2;
    cudaFuncSetAttribute(gemm_attn_kernel<128, false>,
                         cudaFuncAttributeMaxDynamicSharedMemorySize, SMEM128);
    cudaFuncSetAttribute(gemm_attn_kernel<128, true>,
                         cudaFuncAttributeMaxDynamicSharedMemorySize, SMEM128);
    cudaFuncSetAttribute(gemm_attn_kernel<32, true>,
                         cudaFuncAttributeMaxDynamicSharedMemorySize, SMEM32);

    const int TB = 256;
    int aggr_blocks   = (N / 2 + 7) / 8;
    int aggr_blocks8  = (N / 8 + 7) / 8;
    int gemm_blocks   = (N + 63) / 64;
    int gemm_blocks3  = (N + 127) / 128;
    int eb            = (Etot + TB - 1) / TB;
    int nb1 = (N + 255) / 256;             // 196 <= 256

    cudaStream_t s1;
    cudaStreamCreateWithFlags(&s1, cudaStreamNonBlocking);
    cudaEvent_t e1, e2;
    cudaEventCreateWithFlags(&e1, cudaEventDisableTiming);
    cudaEventCreateWithFlags(&e2, cudaEventDisableTiming);

    cudaMemsetAsync(cnt, 0, (size_t)N * sizeof(int));
    cudaEventRecord(e1, 0);
    cudaStreamWaitEvent(s1, e1, 0);

    // s1: CSR build chain
    hist_kernel<<<eb, TB, 0, s1>>>(ei, E, Etot, N, cnt);
    scan_bsum_kernel<<<nb1, 256, 0, s1>>>(cnt, bsum, N);
    // stream 0: wconv + GEMM layer 1 (ncu capture window)
    wconv_kernel<<<144, 256>>>(W1, W2, W3, w16);
    gemm_attn_kernel<128, false><<<gemm_blocks, TB, SMEM128>>>(
        x, nullptr, w16, as1, ad1, xh, als, ald, cs0, N);
    // s1: finish CSR
    scan_bscan_kernel<<<1, 256, 0, s1>>>(bsum, bpre, off, nb1, N);
    scan_write_kernel<<<nb1, 256, 0, s1>>>(cnt, bpre, off, cur, N);
    scatter_kernel<<<eb, TB, 0, s1>>>(ei, E, Etot, cur, csr, dste);
    cudaEventRecord(e2, s1);
    cudaStreamWaitEvent(0, e2, 0);   // join

    // ---- layer 1 weights + aggregation (fp16 agg output) ----
    ew_kernel<<<eb, TB>>>(csr, dste, als, ald, w2, Etot);
    aggr_kernel<128, false><<<aggr_blocks, TB>>>(xh, w2, off, csr, nullptr, agg, cs0, N);

    // ---- layer 2 (PairNorm fused into GEMM A-load, fp16 agg input) ----
    gemm_attn_kernel<128, true><<<gemm_blocks, TB, SMEM128>>>(
        agg, cs0, w16 + 16384, as2, ad2, xh, als, ald, cs1, N);
    ew_kernel<<<eb, TB>>>(csr, dste, als, ald, w2, Etot);
    aggr_kernel<128, false><<<aggr_blocks, TB>>>(xh, w2, off, csr, nullptr, agg, cs1, N);

    // ---- layer 3 (writes d_out with head-mean + bias) ----
    gemm_attn_kernel<32, true><<<gemm_blocks3, TB, SMEM32>>>(
        agg, cs1, w16 + 32768, as3, ad3, xh, als, ald, nullptr, N);
    ew_kernel<<<eb, TB>>>(csr, dste, als, ald, w2, Etot);
    aggr_kernel<32, true><<<aggr_blocks8, TB>>>(xh, w2, off, csr, b3,
                                                (float*)d_out, nullptr, N);
}